// round 9
// baseline (speedup 1.0000x reference)
#include <cuda_runtime.h>

#define HH 128
#define WW 128
#define CC 64
#define OO 64
#define BB 2
#define KK9 9
#define HWSZ (HH*WW)

#define PIX 64          // pixels per main-kernel CTA
#define CH  32          // channels per main-kernel CTA (split-K half)
#define OJ  32          // padded offset-conv output count (27 used)

typedef unsigned long long ull;

// ---------------- f32x2 packed helpers -----------------------------------------
__device__ __forceinline__ ull pack2(float a, float b) {
    ull r; asm("mov.b64 %0, {%1, %2};" : "=l"(r) : "f"(a), "f"(b)); return r;
}
__device__ __forceinline__ ull bcast2(float a) {
    ull r; asm("mov.b64 %0, {%1, %1};" : "=l"(r) : "f"(a)); return r;
}
__device__ __forceinline__ void ffma2(ull& d, ull a, ull b) {
    asm("fma.rn.f32x2 %0, %1, %2, %0;" : "+l"(d) : "l"(a), "l"(b));
}
__device__ __forceinline__ float lo2(ull v) { return __uint_as_float((unsigned)v); }
__device__ __forceinline__ float hi2(ull v) { return __uint_as_float((unsigned)(v >> 32)); }

// ---------------- scratch (__device__ globals) ---------------------------------
__device__ int4   g_sidx[BB*HWSZ*KK9];      // clamped gather indices per (b,pix,k)
__device__ float4 g_swgt[BB*HWSZ*KK9];      // mask-folded bilinear corner weights
__device__ float  g_wt[KK9*CC*OO];          // main weight  -> [k*64+c][o]
__device__ float  g_owt[KK9*CC*OJ];         // offset weight-> [k*64+c][j] (pad 32)
__device__ float  g_part[2][BB*OO*HWSZ];    // split-K partial outputs

// ---------------- K0: weight reorders ------------------------------------------
__global__ __launch_bounds__(256) void reorder_kernel(
    const float* __restrict__ wsrc,   // [64][64][3][3]
    const float* __restrict__ offw)   // [27][64][3][3]
{
    int i = blockIdx.x * 256 + threadIdx.x;
    if (i < OO*CC*KK9) {
        int o = i / (CC*KK9);
        int r = i % (CC*KK9);
        int c = r / KK9;
        int k = r % KK9;
        g_wt[(k*CC + c)*OO + o] = wsrc[i];
    }
    int j = i - OO*CC*KK9;
    if (j >= 0 && j < KK9*CC*OJ) {
        int k  = j / (CC*OJ);
        int r  = j % (CC*OJ);
        int c  = r / OJ;
        int jj = r % OJ;
        g_owt[(k*CC + c)*OJ + jj] =
            (jj < 27) ? offw[jj*(CC*KK9) + c*KK9 + k] : 0.f;
    }
}

// ---------------- K1: offset conv as tap-major GEMM + bilinear precompute ------
// CTA = (b, h, 64-pixel half-row). 256 threads. 9 chunks (tap) x 64 channels.
// Thread tile: 2 outputs x 4 pixels (f32x2 over pixel pairs).
// smem: Ssh[64][64] 16KB | Wsh[64][32] 8KB | ep[32][65] 8.3KB = 32.9 KB.
__global__ __launch_bounds__(256, 5) void offset_kernel(
    const float* __restrict__ x,
    const float* __restrict__ offb)   // [27]
{
    extern __shared__ float sm[];
    float* Ssh = sm;                  // 4096
    float* Wsh = sm + 64*64;          // 2048
    float* ep  = sm + 64*64 + 64*OJ;  // 32*65 = 2080

    int cta = blockIdx.x;
    int wh  = cta & 1;
    int h   = (cta >> 1) & 127;
    int b   = cta >> 8;
    int w0  = wh << 6;
    int t   = threadIdx.x;
    int tx  = t & 15;     // j-pair: j = 2tx, 2tx+1
    int ty  = t >> 4;     // pixel quad: p = 4ty .. 4ty+3

    // bias-initialized accumulators (padded j >= 27 -> 0)
    ull acc2[2][2];
    #pragma unroll
    for (int jp = 0; jp < 2; jp++) {
        int j = 2*tx + jp;
        float bv = (j < 27) ? __ldg(&offb[j]) : 0.f;
        acc2[jp][0] = bcast2(bv);
        acc2[jp][1] = bcast2(bv);
    }

    const float* xb = x + b*CC*HWSZ;

    for (int k = 0; k < KK9; k++) {
        int ki = k / 3, kj = k % 3;
        int row = h + ki - 1;
        int colbase = w0 + kj - 1;
        bool rok = ((unsigned)row < HH);

        __syncthreads();   // previous GEMM reads done

        // stage W chunk: g_owt rows k*64..k*64+63, 8 KB contiguous
        {
            const float4* gw = (const float4*)(g_owt + k*CC*OJ);
            float4* w4 = (float4*)Wsh;
            w4[t]       = gw[t];
            w4[t + 256] = gw[t + 256];
        }

        // stage S chunk: shifted contiguous rows of x (zero-padded)
        const float* xr = xb + row*WW;
        #pragma unroll 4
        for (int i = t; i < 64*64; i += 256) {
            int c = i >> 6;
            int p = i & 63;
            int col = colbase + p;
            float v = (rok && (unsigned)col < WW) ? __ldg(xr + c*HWSZ + col) : 0.f;
            Ssh[i] = v;
        }
        __syncthreads();

        // GEMM: acc[2j x 4p] += W[64c x 32j] * S[64c x 64p]
        #pragma unroll 4
        for (int c = 0; c < 64; c++) {
            float2     wv = *(const float2*)&Wsh[c*OJ + tx*2];
            ulonglong2 sv = *(const ulonglong2*)&Ssh[c*64 + ty*4];
            ull w0b = bcast2(wv.x);
            ull w1b = bcast2(wv.y);
            ffma2(acc2[0][0], w0b, sv.x); ffma2(acc2[0][1], w0b, sv.y);
            ffma2(acc2[1][0], w1b, sv.x); ffma2(acc2[1][1], w1b, sv.y);
        }
    }

    // transpose accumulators to ep[j][p] (stride 65 kills bank conflicts)
    #pragma unroll
    for (int jp = 0; jp < 2; jp++) {
        float* e = ep + (2*tx + jp)*65 + ty*4;
        e[0] = lo2(acc2[jp][0]); e[1] = hi2(acc2[jp][0]);
        e[2] = lo2(acc2[jp][1]); e[3] = hi2(acc2[jp][1]);
    }
    __syncthreads();

    // bilinear epilogue, parallel over (pixel, tap): 576 items
    long base0 = (long)(b*HWSZ + h*WW + w0) * KK9;
    #pragma unroll
    for (int it = 0; it < 3; it++) {
        int idx = t + it*256;
        if (idx < 576) {
            int p = idx / 9;
            int k = idx - p*9;
            int ki = k / 3, kj = k % 3;
            float a1 = ep[k*65 + p];        // dy
            float a2 = ep[(9+k)*65 + p];    // dx
            float a3 = ep[(18+k)*65 + p];   // mask logit
            float py = (float)(h - 1 + ki) + a1;
            float px = (float)(w0 + p - 1 + kj) + a2;
            float m  = 1.f / (1.f + __expf(-a3));
            float y0f = floorf(py), x0f = floorf(px);
            float wy = py - y0f, wx = px - x0f;
            int y0 = (int)y0f, x0 = (int)x0f;
            int y1 = y0 + 1,  x1 = x0 + 1;
            bool v0y = ((unsigned)y0 < HH), v1y = ((unsigned)y1 < HH);
            bool v0x = ((unsigned)x0 < WW), v1x = ((unsigned)x1 < WW);
            float w00 = (v0y && v0x) ? (1.f-wy)*(1.f-wx)*m : 0.f;
            float w01 = (v0y && v1x) ? (1.f-wy)*wx*m       : 0.f;
            float w10 = (v1y && v0x) ? wy*(1.f-wx)*m       : 0.f;
            float w11 = (v1y && v1x) ? wy*wx*m             : 0.f;
            int cy0 = min(max(y0,0),HH-1), cy1 = min(max(y1,0),HH-1);
            int cx0 = min(max(x0,0),WW-1), cx1 = min(max(x1,0),WW-1);
            g_sidx[base0 + p*KK9 + k] =
                make_int4(cy0*WW+cx0, cy0*WW+cx1, cy1*WW+cx0, cy1*WW+cx1);
            g_swgt[base0 + p*KK9 + k] = make_float4(w00, w01, w10, w11);
        }
    }
}

// ---------------- K2: sample + partial GEMM (f32x2), split-K -------------------
// CTA = (b, h, half-row, channel-half). 256 threads. 9 chunks of (tap, 32 ch).
// smem: Wsh[32][64] | Ssh[32][64] = 16 KB  -> 5 CTAs/SM, grid 1024.
__global__ __launch_bounds__(256, 5) void main_kernel(
    const float* __restrict__ x)
{
    extern __shared__ float sm[];
    float* Wsh = sm;                 // 2048 floats
    float* Ssh = sm + CH*PIX;        // 2048 floats

    int cta   = blockIdx.x;
    int chalf = cta & 1;
    int wh    = (cta >> 1) & 1;
    int h     = (cta >> 2) & 127;
    int b     = cta >> 9;
    int pix0  = h*WW + (wh << 6);
    int t = threadIdx.x;

    ull acc2[4][2];
    #pragma unroll
    for (int i = 0; i < 4; i++) { acc2[i][0] = 0ull; acc2[i][1] = 0ull; }

    int tx  = t & 15;    // GEMM: o-tile
    int ty  = t >> 4;    // GEMM: p-tile
    int p   = t & 63;    // sampling: pixel
    int cph = t >> 6;    // sampling: channel phase 0..3

    const float* xb = x + (b*CC + chalf*CH)*HWSZ;
    long mbase = ((long)(b*HWSZ + pix0 + p)) * KK9;

    for (int k = 0; k < KK9; k++) {
        // per-chunk metadata: one sample point per pixel (registers)
        int4   id = __ldg(&g_sidx[mbase + k]);
        float4 wv = __ldg(&g_swgt[mbase + k]);

        __syncthreads();   // previous GEMM reads done

        // load W chunk: rows (k, chalf half), contiguous 8 KB
        {
            const float4* gw = (const float4*)(g_wt + (k*CC + chalf*CH)*OO);
            float4* wsh4 = (float4*)Wsh;
            #pragma unroll
            for (int i = 0; i < 2; i++)
                wsh4[t + i*256] = gw[t + i*256];
        }

        // sampling: 8 channels per thread at the fixed sample point
        #pragma unroll 8
        for (int j = 0; j < 8; j++) {
            int c = cph + j*4;
            const float* xp = xb + c*HWSZ;
            float s = wv.x*__ldg(xp+id.x) + wv.y*__ldg(xp+id.y)
                    + wv.z*__ldg(xp+id.z) + wv.w*__ldg(xp+id.w);
            Ssh[c*PIX + p] = s;
        }
        __syncthreads();

        // partial GEMM: acc += W[32 x 64] * S[32 x 64] tile
        #pragma unroll 4
        for (int c = 0; c < CH; c++) {
            float4     wr = *(const float4*)&Wsh[c*OO  + tx*4];
            ulonglong2 sv = *(const ulonglong2*)&Ssh[c*PIX + ty*4];
            ull w0b = bcast2(wr.x);
            ull w1b = bcast2(wr.y);
            ull w2b = bcast2(wr.z);
            ull w3b = bcast2(wr.w);
            ffma2(acc2[0][0], w0b, sv.x); ffma2(acc2[0][1], w0b, sv.y);
            ffma2(acc2[1][0], w1b, sv.x); ffma2(acc2[1][1], w1b, sv.y);
            ffma2(acc2[2][0], w2b, sv.x); ffma2(acc2[2][1], w2b, sv.y);
            ffma2(acc2[3][0], w3b, sv.x); ffma2(acc2[3][1], w3b, sv.y);
        }
    }

    // write partials (no bias here; K3 adds)
    float* dst = g_part[chalf];
    #pragma unroll
    for (int i = 0; i < 4; i++) {
        int o = tx*4 + i;
        float4 r = make_float4(lo2(acc2[i][0]), hi2(acc2[i][0]),
                               lo2(acc2[i][1]), hi2(acc2[i][1]));
        *(float4*)&dst[(long)(b*OO + o)*HWSZ + pix0 + ty*4] = r;
    }
}

// ---------------- K3: combine split-K partials + bias --------------------------
__global__ __launch_bounds__(256) void combine_kernel(
    const float* __restrict__ bias,
    float* __restrict__ out)
{
    int i = blockIdx.x * 256 + threadIdx.x;          // float4 index
    int o = (i >> 12) & 63;                          // HWSZ/4 = 4096 float4 per o
    float4 a = ((const float4*)g_part[0])[i];
    float4 c = ((const float4*)g_part[1])[i];
    float bv = __ldg(&bias[o]);
    float4 r = make_float4(a.x + c.x + bv, a.y + c.y + bv,
                           a.z + c.z + bv, a.w + c.w + bv);
    ((float4*)out)[i] = r;
}

// ---------------- launch --------------------------------------------------------
extern "C" void kernel_launch(void* const* d_in, const int* in_sizes, int n_in,
                              void* d_out, int out_size)
{
    // identify inputs by element count (robust to ordering)
    const float *x = 0, *wt = 0, *bs = 0, *ow = 0, *ob = 0;
    for (int i = 0; i < n_in; i++) {
        switch (in_sizes[i]) {
            case BB*CC*HWSZ:   x  = (const float*)d_in[i]; break; // 2097152
            case OO*CC*KK9:    wt = (const float*)d_in[i]; break; // 36864
            case OO:           bs = (const float*)d_in[i]; break; // 64
            case 27*CC*KK9:    ow = (const float*)d_in[i]; break; // 15552
            case 27:           ob = (const float*)d_in[i]; break; // 27
        }
    }
    float* out = (float*)d_out;

    const int smem1 = (64*64 + 64*OJ + 32*65) * 4;   // 32896 B
    const int smem2 = 2*CH*PIX*4;                    // 16384 B
    cudaFuncSetAttribute(offset_kernel, cudaFuncAttributeMaxDynamicSharedMemorySize, smem1);
    cudaFuncSetAttribute(main_kernel,  cudaFuncAttributeMaxDynamicSharedMemorySize, smem2);

    int n_reorder = OO*CC*KK9 + KK9*CC*OJ;           // 36864 + 18432
    reorder_kernel<<<(n_reorder + 255)/256, 256>>>(wt, ow);
    offset_kernel<<<BB*HH*2, 256, smem1>>>(x, ob);
    main_kernel<<<BB*HH*2*2, 256, smem2>>>(x);
    combine_kernel<<<(BB*OO*HWSZ/4)/256, 256>>>(bs, out);
}

// round 11
// speedup vs baseline: 1.0764x; 1.0764x over previous
#include <cuda_runtime.h>

#define HH 128
#define WW 128
#define CC 64
#define OO 64
#define BB 2
#define KK9 9
#define HWSZ (HH*WW)

#define PIX 64          // pixels per main-kernel CTA
#define CH  32          // channels per main-kernel CTA (split-K half)

typedef unsigned long long ull;

// ---------------- f32x2 packed helpers -----------------------------------------
__device__ __forceinline__ ull pack2(float a, float b) {
    ull r; asm("mov.b64 %0, {%1, %2};" : "=l"(r) : "f"(a), "f"(b)); return r;
}
__device__ __forceinline__ ull bcast2(float a) {
    ull r; asm("mov.b64 %0, {%1, %1};" : "=l"(r) : "f"(a)); return r;
}
__device__ __forceinline__ void ffma2(ull& d, ull a, ull b) {
    asm("fma.rn.f32x2 %0, %1, %2, %0;" : "+l"(d) : "l"(a), "l"(b));
}
__device__ __forceinline__ void fadd2(ull& d, ull a) {
    asm("add.rn.f32x2 %0, %0, %1;" : "+l"(d) : "l"(a));
}
__device__ __forceinline__ float lo2(ull v) { return __uint_as_float((unsigned)v); }
__device__ __forceinline__ float hi2(ull v) { return __uint_as_float((unsigned)(v >> 32)); }

// ---------------- scratch (__device__ globals) ---------------------------------
__device__ int4   g_sidx[BB*HWSZ*KK9];      // clamped gather indices per (b,pix,k)
__device__ float4 g_swgt[BB*HWSZ*KK9];      // mask-folded bilinear corner weights
__device__ float  g_wt[KK9*CC*OO];          // main weight -> [k*64+c][o]
__device__ float  g_part[2][BB*OO*HWSZ];    // split-K partial outputs

// ---------------- K1: weight reorder + offset conv + bilinear precompute -------
// CTA = (b, h) row. 512 threads = (pixel w 0..127) x (channel quarter 0..3).
// Each thread: 27 conv outputs (14 f32x2) over its 16 channels; quarters
// tree-combined via smem, then cq==0 runs the bilinear epilogue.
// smem: wsh 576*28 floats (64.5 KB) | part 2*128*15 ull (30.7 KB) = 95.2 KB.
__global__ __launch_bounds__(512, 2) void offset_kernel(
    const float* __restrict__ x,
    const float* __restrict__ wsrc,   // [64][64][3][3]  main conv weight
    const float* __restrict__ offw,   // [27][64][3][3]
    const float* __restrict__ offb)   // [27]
{
    extern __shared__ float wsh[];    // 576*28 floats
    ull* part = (ull*)(wsh + 576*28); // [2][128][15]

    int b = blockIdx.x >> 7;
    int h = blockIdx.x & 127;
    int t = threadIdx.x;
    int w  = t & 127;
    int cq = t >> 7;      // channel quarter 0..3

    // main-weight reorder: wsrc[o][c][k] -> g_wt[(k*CC+c)*OO + o]
    // one shot: 256 CTAs x 512 threads = 131072 >= 36864
    {
        int i = blockIdx.x * 512 + t;
        if (i < OO*CC*KK9) {
            int o = i / (CC*KK9);
            int r = i % (CC*KK9);
            int c = r / KK9;
            int k = r % KK9;
            g_wt[(k*CC + c)*OO + o] = wsrc[i];
        }
    }

    // offw[j][ct] -> wsh[ct*28 + j]
    for (int i = t; i < 27*CC*KK9; i += 512) {
        int j  = i / (CC*KK9);
        int ct = i % (CC*KK9);
        wsh[ct*28 + j] = offw[i];
    }
    __syncthreads();

    ull acc2[14];
    if (cq == 0) {
        #pragma unroll
        for (int i = 0; i < 13; i++) acc2[i] = pack2(offb[2*i], offb[2*i+1]);
        acc2[13] = pack2(offb[26], 0.f);
    } else {
        #pragma unroll
        for (int i = 0; i < 14; i++) acc2[i] = 0ull;
    }

    const float* xb = x + b*CC*HWSZ;
    int c0 = cq * 16;
    for (int ci = 0; ci < 16; ci++) {
        int c = c0 + ci;
        float xv[9];
        const float* xp = xb + c*HWSZ;
        #pragma unroll
        for (int ki = 0; ki < 3; ki++) {
            int y = h - 1 + ki;
            bool yok = ((unsigned)y < HH);
            #pragma unroll
            for (int kj = 0; kj < 3; kj++) {
                int xx = w - 1 + kj;
                bool ok = yok && ((unsigned)xx < WW);
                xv[ki*3+kj] = ok ? __ldg(xp + y*WW + xx) : 0.f;
            }
        }
        const float* wc = wsh + c*KK9*28;
        #pragma unroll
        for (int tap = 0; tap < 9; tap++) {
            ull xb2 = bcast2(xv[tap]);
            const ulonglong2* wt2 = (const ulonglong2*)(wc + tap*28);
            #pragma unroll
            for (int j2 = 0; j2 < 7; j2++) {
                ulonglong2 ww = wt2[j2];
                ffma2(acc2[j2*2    ], xb2, ww.x);
                ffma2(acc2[j2*2 + 1], xb2, ww.y);
            }
        }
    }

    // tree combine: (2,3) -> (0,1), then 1 -> 0
    if (cq >= 2) {
        ull* dst = part + (long)(cq - 2)*128*15 + w*15;
        #pragma unroll
        for (int i = 0; i < 14; i++) dst[i] = acc2[i];
    }
    __syncthreads();
    if (cq < 2) {
        ull* src = part + (long)cq*128*15 + w*15;
        #pragma unroll
        for (int i = 0; i < 14; i++) fadd2(acc2[i], src[i]);
    }
    __syncthreads();
    if (cq == 1) {
        ull* dst = part + w*15;
        #pragma unroll
        for (int i = 0; i < 14; i++) dst[i] = acc2[i];
    }
    __syncthreads();
    if (cq != 0) return;

    {
        ull* src = part + w*15;
        #pragma unroll
        for (int i = 0; i < 14; i++) fadd2(acc2[i], src[i]);
    }

    float acc[27];
    #pragma unroll
    for (int j = 0; j < 27; j++)
        acc[j] = (j & 1) ? hi2(acc2[j >> 1]) : lo2(acc2[j >> 1]);

    // derive sample indices + weights
    int pix = h*WW + w;
    long base = (long)(b*HWSZ + pix) * KK9;
    #pragma unroll
    for (int k = 0; k < 9; k++) {
        int ki = k / 3, kj = k % 3;
        float py = (float)(h - 1 + ki) + acc[k];
        float px = (float)(w - 1 + kj) + acc[9+k];
        float m  = 1.f / (1.f + __expf(-acc[18+k]));
        float y0f = floorf(py), x0f = floorf(px);
        float wy = py - y0f, wx = px - x0f;
        int y0 = (int)y0f, x0 = (int)x0f;
        int y1 = y0 + 1,  x1 = x0 + 1;
        bool v0y = ((unsigned)y0 < HH), v1y = ((unsigned)y1 < HH);
        bool v0x = ((unsigned)x0 < WW), v1x = ((unsigned)x1 < WW);
        float w00 = (v0y && v0x) ? (1.f-wy)*(1.f-wx)*m : 0.f;
        float w01 = (v0y && v1x) ? (1.f-wy)*wx*m       : 0.f;
        float w10 = (v1y && v0x) ? wy*(1.f-wx)*m       : 0.f;
        float w11 = (v1y && v1x) ? wy*wx*m             : 0.f;
        int cy0 = min(max(y0,0),HH-1), cy1 = min(max(y1,0),HH-1);
        int cx0 = min(max(x0,0),WW-1), cx1 = min(max(x1,0),WW-1);
        g_sidx[base+k] = make_int4(cy0*WW+cx0, cy0*WW+cx1, cy1*WW+cx0, cy1*WW+cx1);
        g_swgt[base+k] = make_float4(w00, w01, w10, w11);
    }
}

// ---------------- K2: sample + partial GEMM (f32x2), split-K -------------------
// CTA = (b, h, half-row, channel-half). 256 threads. 9 chunks of (tap, 32 ch).
// smem: Wsh[32][64] | Ssh[32][64] = 16 KB  -> 5 CTAs/SM, grid 1024.
__global__ __launch_bounds__(256, 5) void main_kernel(
    const float* __restrict__ x)
{
    extern __shared__ float sm[];
    float* Wsh = sm;                 // 2048 floats
    float* Ssh = sm + CH*PIX;        // 2048 floats

    int cta   = blockIdx.x;
    int chalf = cta & 1;
    int wh    = (cta >> 1) & 1;
    int h     = (cta >> 2) & 127;
    int b     = cta >> 9;
    int pix0  = h*WW + (wh << 6);
    int t = threadIdx.x;

    ull acc2[4][2];
    #pragma unroll
    for (int i = 0; i < 4; i++) { acc2[i][0] = 0ull; acc2[i][1] = 0ull; }

    int tx  = t & 15;    // GEMM: o-tile
    int ty  = t >> 4;    // GEMM: p-tile
    int p   = t & 63;    // sampling: pixel
    int cph = t >> 6;    // sampling: channel phase 0..3

    const float* xb = x + (b*CC + chalf*CH)*HWSZ;
    long mbase = ((long)(b*HWSZ + pix0 + p)) * KK9;

    for (int k = 0; k < KK9; k++) {
        // per-chunk metadata: one sample point per pixel (registers)
        int4   id = __ldg(&g_sidx[mbase + k]);
        float4 wv = __ldg(&g_swgt[mbase + k]);

        __syncthreads();   // previous GEMM reads done

        // load W chunk: rows (k, chalf half), contiguous 8 KB
        {
            const float4* gw = (const float4*)(g_wt + (k*CC + chalf*CH)*OO);
            float4* wsh4 = (float4*)Wsh;
            #pragma unroll
            for (int i = 0; i < 2; i++)
                wsh4[t + i*256] = gw[t + i*256];
        }

        // sampling: 8 channels per thread at the fixed sample point
        #pragma unroll 8
        for (int j = 0; j < 8; j++) {
            int c = cph + j*4;
            const float* xp = xb + c*HWSZ;
            float s = wv.x*__ldg(xp+id.x) + wv.y*__ldg(xp+id.y)
                    + wv.z*__ldg(xp+id.z) + wv.w*__ldg(xp+id.w);
            Ssh[c*PIX + p] = s;
        }
        __syncthreads();

        // partial GEMM: acc += W[32 x 64] * S[32 x 64] tile
        #pragma unroll 4
        for (int c = 0; c < CH; c++) {
            float4     wr = *(const float4*)&Wsh[c*OO  + tx*4];
            ulonglong2 sv = *(const ulonglong2*)&Ssh[c*PIX + ty*4];
            ull w0b = bcast2(wr.x);
            ull w1b = bcast2(wr.y);
            ull w2b = bcast2(wr.z);
            ull w3b = bcast2(wr.w);
            ffma2(acc2[0][0], w0b, sv.x); ffma2(acc2[0][1], w0b, sv.y);
            ffma2(acc2[1][0], w1b, sv.x); ffma2(acc2[1][1], w1b, sv.y);
            ffma2(acc2[2][0], w2b, sv.x); ffma2(acc2[2][1], w2b, sv.y);
            ffma2(acc2[3][0], w3b, sv.x); ffma2(acc2[3][1], w3b, sv.y);
        }
    }

    // write partials (no bias here; K3 adds)
    float* dst = g_part[chalf];
    #pragma unroll
    for (int i = 0; i < 4; i++) {
        int o = tx*4 + i;
        float4 r = make_float4(lo2(acc2[i][0]), hi2(acc2[i][0]),
                               lo2(acc2[i][1]), hi2(acc2[i][1]));
        *(float4*)&dst[(long)(b*OO + o)*HWSZ + pix0 + ty*4] = r;
    }
}

// ---------------- K3: combine split-K partials + bias --------------------------
__global__ __launch_bounds__(256) void combine_kernel(
    const float* __restrict__ bias,
    float* __restrict__ out)
{
    int i = blockIdx.x * 256 + threadIdx.x;          // float4 index
    int o = (i >> 12) & 63;                          // HWSZ/4 = 4096 float4 per o
    float4 a = ((const float4*)g_part[0])[i];
    float4 c = ((const float4*)g_part[1])[i];
    float bv = __ldg(&bias[o]);
    float4 r = make_float4(a.x + c.x + bv, a.y + c.y + bv,
                           a.z + c.z + bv, a.w + c.w + bv);
    ((float4*)out)[i] = r;
}

// ---------------- launch --------------------------------------------------------
extern "C" void kernel_launch(void* const* d_in, const int* in_sizes, int n_in,
                              void* d_out, int out_size)
{
    // identify inputs by element count (robust to ordering)
    const float *x = 0, *wt = 0, *bs = 0, *ow = 0, *ob = 0;
    for (int i = 0; i < n_in; i++) {
        switch (in_sizes[i]) {
            case BB*CC*HWSZ:   x  = (const float*)d_in[i]; break; // 2097152
            case OO*CC*KK9:    wt = (const float*)d_in[i]; break; // 36864
            case OO:           bs = (const float*)d_in[i]; break; // 64
            case 27*CC*KK9:    ow = (const float*)d_in[i]; break; // 15552
            case 27:           ob = (const float*)d_in[i]; break; // 27
        }
    }
    float* out = (float*)d_out;

    const int smem1 = 576*28*4 + 2*128*15*8;   // 64512 + 30720 = 95232 B
    const int smem2 = 2*CH*PIX*4;              // 16384 B
    cudaFuncSetAttribute(offset_kernel, cudaFuncAttributeMaxDynamicSharedMemorySize, smem1);
    cudaFuncSetAttribute(main_kernel,  cudaFuncAttributeMaxDynamicSharedMemorySize, smem2);

    offset_kernel<<<BB*HH, 512, smem1>>>(x, wt, ow, ob);
    main_kernel<<<BB*HH*2*2, 256, smem2>>>(x);
    combine_kernel<<<(BB*OO*HWSZ/4)/256, 256>>>(bs, out);
}